// round 10
// baseline (speedup 1.0000x reference)
#include <cuda_runtime.h>

// DifferentiableCensus: out = (1/9) * sum_{3x3, edge-clamped} sigmoid(neighbor - center)
// x: (16,3,512,512) f32 -> 48 independent 512x512 images.
//
// Round 10: the hidden saturated pipe is XU (MUFU). rt model: EX2/RCP=4,
// tanh.f32=8, tanh.f16x2=16 — explains R2..R9 all pinning at 21us.
// Fix: dual-pipe sigmoid evaluation.
//  - S/SE/SW edges (12/row): tanh.approx.f32          (8 XU cyc each)
//  - E + halo edges (7/row):  EX2 + deg-5 Chebyshev   (4 XU + 7 FMA each)
//      t = sign(d) * (2*R(u)-1),  u = 2^(-|d|*log2 e) in (0,1],
//      R(u) ~ 1/(1+u): exact Chebyshev of 1/(3+s), s=2u-1, err 4.4e-5,
//      globally valid (no clamp, no division).
//  - Edge-sharing algebra unchanged: each pixel-pair edge once, reverse = -t.
//  - out = 0.5 + T/18.

static constexpr int H = 512;
static constexpr int W = 512;
static constexpr int ROWS_PER_THREAD = 8;
static constexpr int BLOCK_X = 128;            // 128 threads * 4 cols = 512 cols

__device__ __forceinline__ float tanh_ap(float v) {
    float r;
    asm("tanh.approx.f32 %0, %1;" : "=f"(r) : "f"(v));
    return r;
}

__device__ __forceinline__ float ex2_ap(float v) {
    float r;
    asm("ex2.approx.f32 %0, %1;" : "=f"(r) : "f"(v));
    return r;
}

// tanh(ps) for prescaled ps = d/2, via FMA-pipe polynomial + 1 EX2.
// G(s) = 2/(1+u) - 1, s = 2u-1, u = exp(-|d|) = 2^(-|ps|*2.885390);
// monomial coeffs from the exact Chebyshev series of 1/(3+s) (deg 5).
__device__ __forceinline__ float sig_poly(float ps) {
    const float a = fabsf(ps) * -2.8853900817779268f;   // -|d|*log2(e)
    const float u = ex2_ap(a);                          // XU: EX2 (rt 4)
    const float s = fmaf(2.0f, u, -1.0f);
    float p = fmaf(-0.00672928f, s, 0.01960928f);
    p = fmaf(p, s, -0.04872832f);
    p = fmaf(p, s,  0.14691296f);
    p = fmaf(p, s, -0.44452934f);
    p = fmaf(p, s,  0.33340360f);                       // p = 2*R(u)-1 >= ~0
    return copysignf(p, ps);                            // ALU: sign transfer
}

__device__ __forceinline__ void load_row(const float* __restrict__ row,
                                         int c0, int cl, int cr, float v[6]) {
    // v[0]=col c0-1 (clamped), v[1..4]=c0..c0+3, v[5]=c0+4 (clamped); prescaled 0.5
    const float4 m = __ldg(reinterpret_cast<const float4*>(row + c0));
    v[0] = 0.5f * __ldg(row + cl);
    v[1] = 0.5f * m.x;
    v[2] = 0.5f * m.y;
    v[3] = 0.5f * m.z;
    v[4] = 0.5f * m.w;
    v[5] = 0.5f * __ldg(row + cr);
}

__global__ __launch_bounds__(BLOCK_X)
void census_kernel(const float* __restrict__ x, float* __restrict__ out) {
    const int c0  = threadIdx.x * 4;
    const int r0  = blockIdx.y * ROWS_PER_THREAD;
    const int img = blockIdx.z;

    const float* __restrict__ xi = x   + (size_t)img * H * W;
    float* __restrict__       oi = out + (size_t)img * H * W;

    const int cl = max(c0 - 1, 0);
    const int cr = min(c0 + 4, W - 1);

    float b[6];
    load_row(xi + (size_t)r0 * W, c0, cl, cr, b);

    // Priming carries from row r0-1 (p): S/SE/SW edge tanh + p's halo lanes.
    float pS[4], pDR[4], pDL[4], pl, pr;
    {
        float p[6];
        load_row(xi + (size_t)max(r0 - 1, 0) * W, c0, cl, cr, p);
        #pragma unroll
        for (int i = 0; i < 4; i++) {
            pS[i]  = tanh_ap(b[i + 1] - p[i + 1]);
            pDR[i] = tanh_ap(b[i + 2] - p[i + 1]);
            pDL[i] = tanh_ap(b[i]     - p[i + 1]);
        }
        pl = p[0]; pr = p[5];
    }

    #pragma unroll
    for (int k = 0; k < ROWS_PER_THREAD; k++) {
        const int r = r0 + k;
        float n[6];
        load_row(xi + (size_t)min(r + 1, H - 1) * W, c0, cl, cr, n);

        // XU path: S / SE / SW (forward edges to the next row).
        float tS[4], tDR[4], tDL[4];
        #pragma unroll
        for (int i = 0; i < 4; i++) {
            tS[i]  = tanh_ap(n[i + 1] - b[i + 1]); // S
            tDR[i] = tanh_ap(n[i + 2] - b[i + 1]); // SE
            tDL[i] = tanh_ap(n[i]     - b[i + 1]); // SW
        }

        // FMA path: horizontal + halo edges (depend only on rows b, p-halo).
        float tE[4];
        #pragma unroll
        for (int i = 0; i < 4; i++)
            tE[i] = sig_poly(b[i + 2] - b[i + 1]); // E
        const float tW0  = sig_poly(b[0] - b[1]);  // W  halo (col c0)
        const float tUL0 = sig_poly(pl   - b[1]);  // NW halo (col c0)
        const float tUR3 = sig_poly(pr   - b[4]);  // NE halo (col c0+3)

        // Signed sums: forward edges +, reverse of previously-computed edges -.
        const float T0 = (tS[0] + tDR[0]) + (tDL[0] - pS[0])
                       + (tE[0] + tW0)    + (tUL0   - pDL[1]);
        const float T1 = (tS[1] + tDR[1]) + (tDL[1] - pS[1])
                       + (tE[1] - tE[0])  - (pDR[0] + pDL[2]);
        const float T2 = (tS[2] + tDR[2]) + (tDL[2] - pS[2])
                       + (tE[2] - tE[1])  - (pDR[1] + pDL[3]);
        const float T3 = (tS[3] + tDR[3]) + (tDL[3] - pS[3])
                       + (tE[3] - tE[2])  + (tUR3   - pDR[2]);

        float4 o;
        o.x = fmaf(T0, 1.0f / 18.0f, 0.5f);
        o.y = fmaf(T1, 1.0f / 18.0f, 0.5f);
        o.z = fmaf(T2, 1.0f / 18.0f, 0.5f);
        o.w = fmaf(T3, 1.0f / 18.0f, 0.5f);
        *reinterpret_cast<float4*>(oi + (size_t)r * W + c0) = o;

        // Roll: keep old center row's halo lanes; carry forward edges.
        pl = b[0]; pr = b[5];
        #pragma unroll
        for (int i = 0; i < 6; i++) b[i] = n[i];
        #pragma unroll
        for (int i = 0; i < 4; i++) { pS[i] = tS[i]; pDR[i] = tDR[i]; pDL[i] = tDL[i]; }
    }
}

extern "C" void kernel_launch(void* const* d_in, const int* in_sizes, int n_in,
                              void* d_out, int out_size) {
    (void)in_sizes; (void)n_in; (void)out_size;
    const float* x = (const float*)d_in[0];
    float* out = (float*)d_out;

    dim3 block(BLOCK_X, 1, 1);
    dim3 grid(1, H / ROWS_PER_THREAD, 16 * 3);
    census_kernel<<<grid, block>>>(x, out);
}

// round 11
// speedup vs baseline: 1.1951x; 1.1951x over previous
#include <cuda_runtime.h>

// DifferentiableCensus: out = (1/9) * sum_{3x3, edge-clamped} sigmoid(neighbor - center)
// x: (16,3,512,512) f32 -> 48 independent 512x512 images.
//
// Round 11: memory-floor hypothesis. Steady-state DRAM traffic == output
// write-drain (~50MB @ ~2.7TB/s ~= 19-21us) -> SM-side work is subcritical.
//  - Leanest datapath (R8): f32 tanh.approx, edge-sharing (each pixel-pair
//    edge once; reverse = negation), out = 0.5 + T/18.
//  - __stcs evict-first stores: keep input L2-resident across replays.
//  - 16 rows/thread, grid = 1536 CTAs = one balanced wave (no tail).

static constexpr int H = 512;
static constexpr int W = 512;
static constexpr int ROWS_PER_THREAD = 16;
static constexpr int BLOCK_X = 128;            // 128 threads * 4 cols = 512 cols

__device__ __forceinline__ float tanh_ap(float v) {
    float r;
    asm("tanh.approx.f32 %0, %1;" : "=f"(r) : "f"(v));
    return r;
}

__device__ __forceinline__ void load_row(const float* __restrict__ row,
                                         int c0, int cl, int cr, float v[6]) {
    // v[0]=col c0-1 (clamped), v[1..4]=c0..c0+3, v[5]=c0+4 (clamped); prescaled 0.5
    const float4 m = __ldg(reinterpret_cast<const float4*>(row + c0));
    v[0] = 0.5f * __ldg(row + cl);
    v[1] = 0.5f * m.x;
    v[2] = 0.5f * m.y;
    v[3] = 0.5f * m.z;
    v[4] = 0.5f * m.w;
    v[5] = 0.5f * __ldg(row + cr);
}

__global__ __launch_bounds__(BLOCK_X)
void census_kernel(const float* __restrict__ x, float* __restrict__ out) {
    const int c0  = threadIdx.x * 4;
    const int r0  = blockIdx.y * ROWS_PER_THREAD;
    const int img = blockIdx.z;

    const float* __restrict__ xi = x   + (size_t)img * H * W;
    float* __restrict__       oi = out + (size_t)img * H * W;

    const int cl = max(c0 - 1, 0);
    const int cr = min(c0 + 4, W - 1);

    float b[6];
    load_row(xi + (size_t)r0 * W, c0, cl, cr, b);

    // Priming carries from row r0-1 (p): S/SE/SW edge tanh + p's halo lanes.
    float pS[4], pDR[4], pDL[4], pl, pr;
    {
        float p[6];
        load_row(xi + (size_t)max(r0 - 1, 0) * W, c0, cl, cr, p);
        #pragma unroll
        for (int i = 0; i < 4; i++) {
            pS[i]  = tanh_ap(b[i + 1] - p[i + 1]);
            pDR[i] = tanh_ap(b[i + 2] - p[i + 1]);
            pDL[i] = tanh_ap(b[i]     - p[i + 1]);
        }
        pl = p[0]; pr = p[5];
    }

    #pragma unroll
    for (int k = 0; k < ROWS_PER_THREAD; k++) {
        const int r = r0 + k;
        float n[6];
        load_row(xi + (size_t)min(r + 1, H - 1) * W, c0, cl, cr, n);

        float tS[4], tDR[4], tDL[4], tE[4];
        #pragma unroll
        for (int i = 0; i < 4; i++) {
            tS[i]  = tanh_ap(n[i + 1] - b[i + 1]); // S
            tDR[i] = tanh_ap(n[i + 2] - b[i + 1]); // SE
            tDL[i] = tanh_ap(n[i]     - b[i + 1]); // SW
            tE[i]  = tanh_ap(b[i + 2] - b[i + 1]); // E
        }
        const float tW0  = tanh_ap(b[0] - b[1]);   // W  halo (col c0)
        const float tUL0 = tanh_ap(pl   - b[1]);   // NW halo (col c0)
        const float tUR3 = tanh_ap(pr   - b[4]);   // NE halo (col c0+3)

        // Signed sums: forward edges +, reverse of previously-computed edges -.
        const float T0 = (tS[0] + tDR[0]) + (tDL[0] - pS[0])
                       + (tE[0] + tW0)    + (tUL0   - pDL[1]);
        const float T1 = (tS[1] + tDR[1]) + (tDL[1] - pS[1])
                       + (tE[1] - tE[0])  - (pDR[0] + pDL[2]);
        const float T2 = (tS[2] + tDR[2]) + (tDL[2] - pS[2])
                       + (tE[2] - tE[1])  - (pDR[1] + pDL[3]);
        const float T3 = (tS[3] + tDR[3]) + (tDL[3] - pS[3])
                       + (tE[3] - tE[2])  + (tUR3   - pDR[2]);

        float4 o;
        o.x = fmaf(T0, 1.0f / 18.0f, 0.5f);
        o.y = fmaf(T1, 1.0f / 18.0f, 0.5f);
        o.z = fmaf(T2, 1.0f / 18.0f, 0.5f);
        o.w = fmaf(T3, 1.0f / 18.0f, 0.5f);
        // Evict-first store: output is never re-read; don't pollute L2.
        __stcs(reinterpret_cast<float4*>(oi + (size_t)r * W + c0), o);

        // Roll: keep old center row's halo lanes; carry forward edges.
        pl = b[0]; pr = b[5];
        #pragma unroll
        for (int i = 0; i < 6; i++) b[i] = n[i];
        #pragma unroll
        for (int i = 0; i < 4; i++) { pS[i] = tS[i]; pDR[i] = tDR[i]; pDL[i] = tDL[i]; }
    }
}

extern "C" void kernel_launch(void* const* d_in, const int* in_sizes, int n_in,
                              void* d_out, int out_size) {
    (void)in_sizes; (void)n_in; (void)out_size;
    const float* x = (const float*)d_in[0];
    float* out = (float*)d_out;

    dim3 block(BLOCK_X, 1, 1);
    dim3 grid(1, H / ROWS_PER_THREAD, 16 * 3);   // 1536 CTAs ~= one balanced wave
    census_kernel<<<grid, block>>>(x, out);
}